// round 1
// baseline (speedup 1.0000x reference)
#include <cuda_runtime.h>

// Problem shape is fixed by setup_inputs(): B=16, C=1024, H=W=32, NH=16.
#define B_  16
#define C_  1024
#define H_  32
#define W_  32
#define HW_ (H_*W_)
#define NH_ 16
#define P_  (H_*W_)       // 1024
#define N_  (P_+1)        // 1025
#define K_  10

// Scratch (no allocations allowed): ratio, top-k indices, winner bitmasks.
__device__ float         g_ratio[B_][P_];
__device__ int           g_idx[B_][K_];
__device__ unsigned char g_win[B_][K_];

__constant__ int c_dy[8] = {-1,-1,-1, 0, 0, 1, 1, 1};
__constant__ int c_dx[8] = {-1, 0, 1,-1, 1,-1, 0, 1};

// ---------------------------------------------------------------------------
// Kernel 1: ratio[b][p] = mean_h attn[b,h,0,1+p] / (mean_h attn[b,h,1+p,1+p] + 1e-8)
// grid (B, P/128), 128 threads. 32 independent loads in flight per thread.
// ---------------------------------------------------------------------------
__global__ void ratio_kernel(const float* __restrict__ attn) {
    int b = blockIdx.x;
    int p = blockIdx.y * 128 + threadIdx.x;
    const float* base = attn + (size_t)b * NH_ * (size_t)N_ * N_;
    size_t diag = (size_t)(1 + p) * N_ + (1 + p);
    float cls = 0.f, slf = 0.f;
#pragma unroll
    for (int h = 0; h < NH_; h++) {
        const float* a = base + (size_t)h * N_ * N_;
        cls += a[1 + p];
        slf += a[diag];
    }
    cls *= (1.f / NH_);
    slf *= (1.f / NH_);
    g_ratio[b][p] = cls / (slf + 1e-8f);
}

// ---------------------------------------------------------------------------
// Kernel 2: top-10 (value desc, tie -> lower index, matching jax.lax.top_k),
// plus last-writer-wins "winner" bitmask per (outlier, neighbor) slot.
// grid B, 1024 threads.
// ---------------------------------------------------------------------------
__global__ void topk_kernel() {
    int b = blockIdx.x;
    int t = threadIdx.x;
    __shared__ unsigned long long keys[P_];
    __shared__ unsigned long long red[P_];

    // ratio >= 0, so float bit pattern is monotonic as unsigned.
    float rt = g_ratio[b][t];
    keys[t] = ((unsigned long long)__float_as_uint(rt) << 32)
            | (unsigned)(0xFFFFFFFFu - (unsigned)t);   // tie -> smaller index wins
    __syncthreads();

    for (int k = 0; k < K_; k++) {
        red[t] = keys[t];
        __syncthreads();
        for (int s = P_ / 2; s >= 1; s >>= 1) {
            if (t < s) {
                unsigned long long o = red[t + s];
                if (o > red[t]) red[t] = o;
            }
            __syncthreads();
        }
        int bi = (int)(0xFFFFFFFFu - (unsigned)(red[0] & 0xFFFFFFFFull));
        if (t == bi) keys[t] = 0ull;                   // remove selected
        if (t == 0) g_idx[b][k] = bi;
        __syncthreads();
    }

    if (t == 0) {
        int rr[K_], cc[K_];
#pragma unroll
        for (int i = 0; i < K_; i++) {
            int p = g_idx[b][i];
            rr[i] = p / W_; cc[i] = p % W_;
        }
        unsigned char wm[K_];
        for (int i = 0; i < K_; i++) wm[i] = 0;
        int cy[K_ * 8], cx[K_ * 8]; int ncl = 0;
        // Walk slots from highest k down: first claimant of a non-center
        // position is the last writer in the reference's sequential loop.
        for (int k = K_ * 8 - 1; k >= 0; k--) {
            int i = k >> 3, j = k & 7;
            int y = rr[i] + c_dy[j]; y = y < 0 ? 0 : (y > H_ - 1 ? H_ - 1 : y);
            int x = cc[i] + c_dx[j]; x = x < 0 ? 0 : (x > W_ - 1 ? W_ - 1 : x);
            bool skip = false;
            for (int m = 0; m < K_; m++)
                if (y == rr[m] && x == cc[m]) { skip = true; break; }  // centers end as wavg
            if (skip) continue;
            for (int m = 0; m < ncl; m++)
                if (cy[m] == y && cx[m] == x) { skip = true; break; }  // later slot already wrote
            if (skip) continue;
            cy[ncl] = y; cx[ncl] = x; ncl++;
            wm[i] |= (unsigned char)(1u << j);
        }
        for (int i = 0; i < K_; i++) g_win[b][i] = wm[i];
    }
}

// ---------------------------------------------------------------------------
// Kernel 3: bulk copy fm -> out (the roofline floor: 128 MB of traffic).
// ---------------------------------------------------------------------------
__global__ void copy_kernel(const float4* __restrict__ in, float4* __restrict__ out, int n) {
    int i = blockIdx.x * blockDim.x + threadIdx.x;
    int stride = gridDim.x * blockDim.x;
    for (; i < n; i += stride) out[i] = in[i];
}

// ---------------------------------------------------------------------------
// Kernel 4: suppression. One block per (batch, outlier) = 160 blocks, 256 thr.
// All reads from original fm; writes only to winner slots + own center,
// which are globally disjoint -> race-free.
// ---------------------------------------------------------------------------
__global__ void __launch_bounds__(256) suppress_kernel(const float* __restrict__ fm,
                                                       float* __restrict__ out) {
    int blk = blockIdx.x;
    int b = blk / K_, i = blk % K_;
    int p = g_idx[b][i];
    int r = p / W_, c = p % W_;
    unsigned win = g_win[b][i];

    int ny[8], nx[8];
#pragma unroll
    for (int j = 0; j < 8; j++) {
        int y = r + c_dy[j]; ny[j] = y < 0 ? 0 : (y > H_ - 1 ? H_ - 1 : y);
        int x = c + c_dx[j]; nx[j] = x < 0 ? 0 : (x > W_ - 1 ? W_ - 1 : x);
    }

    const float* f = fm  + (size_t)b * C_ * HW_;
    float*       o = out + (size_t)b * C_ * HW_;
    int t = threadIdx.x;

    float ov[4];
    float nb[8][4];
    float dot[8] = {0,0,0,0,0,0,0,0};
    float n2[8]  = {0,0,0,0,0,0,0,0};
    float o2 = 0.f;

#pragma unroll
    for (int u = 0; u < 4; u++) {
        int ch = t + u * 256;
        float v = f[(size_t)ch * HW_ + r * W_ + c];
        ov[u] = v;
        o2 += v * v;
#pragma unroll
        for (int j = 0; j < 8; j++) {
            float nv = f[(size_t)ch * HW_ + ny[j] * W_ + nx[j]];
            nb[j][u] = nv;
            dot[j] += nv * v;
            n2[j]  += nv * nv;
        }
    }

    // Block-reduce 17 partial sums (o2, dot[8], n2[8]).
    __shared__ float part[17][8];
    float vals[17];
    vals[0] = o2;
#pragma unroll
    for (int j = 0; j < 8; j++) { vals[1 + j] = dot[j]; vals[9 + j] = n2[j]; }
#pragma unroll
    for (int k = 0; k < 17; k++) {
        float v = vals[k];
#pragma unroll
        for (int off = 16; off; off >>= 1) v += __shfl_down_sync(0xffffffffu, v, off);
        if ((t & 31) == 0) part[k][t >> 5] = v;
    }
    __syncthreads();

    __shared__ float s_w[8], s_str[8];
    if (t == 0) {
        float sums[17];
#pragma unroll
        for (int k = 0; k < 17; k++) {
            float s = 0.f;
#pragma unroll
            for (int wrp = 0; wrp < 8; wrp++) s += part[k][wrp];
            sums[k] = s;
        }
        float on = fmaxf(sqrtf(sums[0]), 1e-12f);
        float sim[8], z[8];
        float zmax = -1e30f;
#pragma unroll
        for (int j = 0; j < 8; j++) {
            float nn = fmaxf(sqrtf(sums[9 + j]), 1e-12f);
            sim[j] = sums[1 + j] / (nn * on);
            z[j] = fmaxf(1.f - sim[j], 0.f);
            zmax = fmaxf(zmax, z[j]);
        }
        float es = 0.f, e[8];
#pragma unroll
        for (int j = 0; j < 8; j++) { e[j] = expf(z[j] - zmax); es += e[j]; }
        float inv = 1.f / es;
#pragma unroll
        for (int j = 0; j < 8; j++) {
            s_w[j]   = e[j] * inv;
            s_str[j] = fminf(fmaxf(sim[j] * 0.1f, 0.f), 1.f);
        }
    }
    __syncthreads();

    float w[8], str[8];
#pragma unroll
    for (int j = 0; j < 8; j++) { w[j] = s_w[j]; str[j] = s_str[j]; }

#pragma unroll
    for (int u = 0; u < 4; u++) {
        int ch = t + u * 256;
        float wa = 0.f;
#pragma unroll
        for (int j = 0; j < 8; j++) wa += nb[j][u] * w[j];
        o[(size_t)ch * HW_ + r * W_ + c] = wa;                       // center <- wavg
#pragma unroll
        for (int j = 0; j < 8; j++) {
            if ((win >> j) & 1u)
                o[(size_t)ch * HW_ + ny[j] * W_ + nx[j]] = nb[j][u] - ov[u] * str[j];
        }
    }
}

// ---------------------------------------------------------------------------
extern "C" void kernel_launch(void* const* d_in, const int* in_sizes, int n_in,
                              void* d_out, int out_size) {
    const float* fm   = (const float*)d_in[0];
    const float* attn = (const float*)d_in[1];
    float* out = (float*)d_out;

    ratio_kernel<<<dim3(B_, P_ / 128), 128>>>(attn);
    topk_kernel<<<B_, P_>>>();
    copy_kernel<<<2048, 256>>>((const float4*)fm, (float4*)out, (B_ * C_ * HW_) / 4);
    suppress_kernel<<<B_ * K_, 256>>>(fm, out);
}